// round 11
// baseline (speedup 1.0000x reference)
#include <cuda_runtime.h>
#include <cuda_fp16.h>
#include <cstdint>
#include <cstddef>

#define HID 1024
#define BAT 512
#define NL  2
#define TT  32

#define A_BYTES   16384          // 128 rows x 64 halves
#define B_BYTES   14336          // 112 rows x 64 halves (max col-tile)
#define STG_BYTES (A_BYTES + B_BYTES)   // 30720
#define NSTG 6
#define SMEM_BYTES (NSTG * STG_BYTES)   // 184320, 1 CTA/SM

// ---------------- device scratch ----------------
__device__ __half g_Wc[(size_t)NL * 4 * HID * 2 * HID];  // [l][np][k] gate-interleaved, K-concat
__device__ __half g_thW[(size_t)2 * HID * HID];
__device__ float  g_biasc[NL * 4 * HID];
__device__ __half g_z16[(size_t)BAT * HID];
__device__ __half g_x0[(size_t)BAT * HID];
__device__ __half g_h[NL * 2][(size_t)BAT * HID];        // ping-pong per layer
__device__ float  g_c[NL][(size_t)BAT * HID];

// ---------------- helpers ----------------
__device__ __forceinline__ uint32_t smem_u32(const void* p) {
    return (uint32_t)__cvta_generic_to_shared(p);
}
__device__ __forceinline__ void cp16(uint32_t s, const void* g) {
    asm volatile("cp.async.cg.shared.global [%0], [%1], 16;\n" :: "r"(s), "l"(g));
}
__device__ __forceinline__ void mma16816(float* d, const uint32_t* a, const uint32_t* b) {
    asm volatile(
        "mma.sync.aligned.m16n8k16.row.col.f32.f16.f16.f32 "
        "{%0,%1,%2,%3}, {%4,%5,%6,%7}, {%8,%9}, {%0,%1,%2,%3};\n"
        : "+f"(d[0]), "+f"(d[1]), "+f"(d[2]), "+f"(d[3])
        : "r"(a[0]), "r"(a[1]), "r"(a[2]), "r"(a[3]), "r"(b[0]), "r"(b[1]));
}
#define LDSM4(r, addr)                                                          \
    asm volatile("ldmatrix.sync.aligned.m8n8.x4.shared.b16 {%0,%1,%2,%3}, [%4];"\
        : "=r"((r)[0]), "=r"((r)[1]), "=r"((r)[2]), "=r"((r)[3]) : "r"(addr))

// smem tile rows of 64 halves (128B), classic 8-chunk xor swizzle
__device__ __forceinline__ int swz64(int r, int k) {
    return r * 64 + ((((k >> 3) ^ (r & 7)) << 3) | (k & 7));
}

__device__ __forceinline__ float sigf(float x) {
    return __fdividef(1.f, 1.f + __expf(-x));
}
__device__ __forceinline__ float tanhe(float x) {
    return __fdividef(2.f, 1.f + __expf(-2.f * x)) - 1.f;
}

// ---------------- conversion kernels ----------------
// gate-interleaved: np = 16*(u>>2) + 2*(u&3) + gofs, gofs = {i:0, f:1, g:8, o:9}
__global__ void convert_w_kernel(const float* __restrict__ Wih, const float* __restrict__ Whh) {
    size_t total = (size_t)NL * 4 * HID * 2 * HID;
    for (size_t idx = (size_t)blockIdx.x * blockDim.x + threadIdx.x; idx < total;
         idx += (size_t)gridDim.x * blockDim.x) {
        int k  = (int)(idx & (2 * HID - 1));
        int np = (int)((idx >> 11) & 4095);
        int l  = (int)(idx >> 23);
        int within = np & 15, block = np >> 4;
        int gate = ((within & 8) ? 2 : 0) + (within & 1);
        int tig  = (within & 7) >> 1;
        int u = block * 4 + tig;
        size_t ln = (size_t)l * 4 * HID + (size_t)gate * HID + u;
        float v = (k < HID) ? Wih[ln * HID + k] : Whh[ln * HID + (k - HID)];
        g_Wc[idx] = __float2half(v);
    }
}
__global__ void convert_misc_kernel(const float* __restrict__ z, const float* __restrict__ thW,
                                    const float* __restrict__ emb,
                                    const float* __restrict__ bih, const float* __restrict__ bhh) {
    int total = 2 * HID * HID;
    for (int idx = blockIdx.x * blockDim.x + threadIdx.x; idx < total;
         idx += gridDim.x * blockDim.x) {
        g_thW[idx] = __float2half(thW[idx]);
        if (idx < BAT * HID) {
            g_z16[idx] = __float2half(z[idx]);
            g_x0[idx]  = __float2half(emb[idx & (HID - 1)]);
        }
        if (idx < NL * BAT * HID) ((float*)g_c)[idx] = 0.f;
        if (idx < NL * 4 * HID) {
            int l = idx >> 12, np = idx & 4095;
            int within = np & 15, block = np >> 4;
            int gate = ((within & 8) ? 2 : 0) + (within & 1);
            int tig  = (within & 7) >> 1;
            int u = block * 4 + tig;
            int src = l * 4 * HID + gate * HID + u;
            g_biasc[idx] = bih[src] + bhh[src];
        }
    }
}

// ---------------- fused GEMM (+LSTM cell), 148-CTA ragged column tiling ------
// C[512,Ntot] = [A0|A1][512,K] @ Bw[Ntot,K]^T
// CTA tile 128(M) x W(N), W = min(112, Ntot - 112*bx), 16 warps (4m x 4n).
// n-warp wn owns 16-col gate blocks {wn, wn+4} (guarded by nblocks).
// 6-stage cp.async ring, one barrier per PAIR of 64-half k-tiles,
// register double-buffered fragments within each pair.
template<int EPI>
__global__ void __launch_bounds__(512)
lstm_gemm(const __half* __restrict__ A0, const __half* __restrict__ A1,
          const __half* __restrict__ Bw, const float* __restrict__ bias,
          float* __restrict__ cptr, __half* __restrict__ hptr,
          float* __restrict__ yptr, int KT, int Ntot)  // KT in 64-half k-tiles (even)
{
    extern __shared__ __half sm[];
    const uint32_t sb = smem_u32(sm);
    const int tid = threadIdx.x, wid = tid >> 5, lane = tid & 31;
    const int g8 = lane >> 2, tig = lane & 3;
    const int wm = wid & 3, wn = wid >> 2;             // 4m x 4n warps
    const int bm = blockIdx.y * 128, bn = blockIdx.x * 112;
    const int nblocks = min(7, (Ntot - bn) >> 4);      // 16-col blocks in this tile
    const int W = nblocks << 4;
    const bool hb0 = (wn < nblocks), hb1 = (wn + 4 < nblocks);
    const int Kh = KT * 64;
    const int NP = KT >> 1;

    float acc[2][2][2][4];                              // [mt][bt][n8][4]
    #pragma unroll
    for (int a = 0; a < 2; a++)
        #pragma unroll
        for (int b = 0; b < 2; b++)
            #pragma unroll
            for (int q = 0; q < 2; q++)
                #pragma unroll
                for (int d = 0; d < 4; d++) acc[a][b][q][d] = 0.f;

    // slice-0 tile-relative byte offsets; slice s: off ^ (s<<5)
    uint32_t aoff[2], boff[2];
    {
        int arow = lane & 15, ac = (lane >> 4) << 3;
        int brow = (lane & 7) + ((lane & 16) >> 1), bc = lane & 8;
        #pragma unroll
        for (int mt = 0; mt < 2; mt++)
            aoff[mt] = 2 * swz64(wm * 32 + mt * 16 + arow, ac);
        #pragma unroll
        for (int bt = 0; bt < 2; bt++) {
            int lb = wn + 4 * bt;
            int lbc = (lb < 7) ? lb : 0;               // clamp (guarded out anyway)
            boff[bt] = A_BYTES + 2 * swz64(lbc * 16 + brow, bc);
        }
    }

    auto fill = [&](int kt) {
        int st = kt % NSTG;
        int k0 = kt << 6;
        const __half* Ap; int ks;
        if (k0 < HID) { Ap = A0; ks = k0; } else { Ap = A1; ks = k0 - HID; }
        uint32_t ab = sb + st * STG_BYTES, bb = ab + A_BYTES;
        #pragma unroll
        for (int i = 0; i < 2; i++) {                  // A: 1024 chunks of 16B
            int idx = tid + i * 512;
            int r = idx >> 3, c = idx & 7;
            cp16(ab + 2 * swz64(r, c << 3), Ap + (size_t)(bm + r) * HID + ks + (c << 3));
        }
        #pragma unroll
        for (int i = 0; i < 2; i++) {                  // B: W*8 chunks (<=896)
            int idx = tid + i * 512;
            int r = idx >> 3, c = idx & 7;
            if (r < W)
                cp16(bb + 2 * swz64(r, c << 3), Bw + (size_t)(bn + r) * Kh + k0 + (c << 3));
        }
    };

    fill(0); fill(1); asm volatile("cp.async.commit_group;\n");
    if (NP > 1) { fill(2); fill(3); asm volatile("cp.async.commit_group;\n"); }

    for (int i = 0; i < NP; i++) {
        if (i + 1 < NP) asm volatile("cp.async.wait_group 1;\n");
        else            asm volatile("cp.async.wait_group 0;\n");
        __syncthreads();
        if (i + 2 < NP) {
            fill(2 * i + 4); fill(2 * i + 5);
            asm volatile("cp.async.commit_group;\n");
        }

        const uint32_t base0 = sb + ((2 * i) % NSTG) * STG_BYTES;
        const uint32_t base1 = sb + ((2 * i + 1) % NSTG) * STG_BYTES;

        uint32_t af[2][2][4], bf[2][2][4];
        #pragma unroll
        for (int mt = 0; mt < 2; mt++) LDSM4(af[0][mt], base0 + aoff[mt]);
        if (hb0) LDSM4(bf[0][0], base0 + boff[0]);
        if (hb1) LDSM4(bf[0][1], base0 + boff[1]);

        #pragma unroll
        for (int ss = 0; ss < 8; ss++) {
            const int cb = ss & 1, nb = cb ^ 1;
            if (ss < 7) {
                const int ns = ss + 1;
                const uint32_t nbase = (ns < 4) ? base0 : base1;
                const uint32_t x = (uint32_t)(ns & 3) << 5;
                #pragma unroll
                for (int mt = 0; mt < 2; mt++) LDSM4(af[nb][mt], nbase + (aoff[mt] ^ x));
                if (hb0) LDSM4(bf[nb][0], nbase + (boff[0] ^ x));
                if (hb1) LDSM4(bf[nb][1], nbase + (boff[1] ^ x));
            }
            #pragma unroll
            for (int mt = 0; mt < 2; mt++) {
                if (hb0) {
                    mma16816(acc[mt][0][0], af[cb][mt], &bf[cb][0][0]);
                    mma16816(acc[mt][0][1], af[cb][mt], &bf[cb][0][2]);
                }
                if (hb1) {
                    mma16816(acc[mt][1][0], af[cb][mt], &bf[cb][1][0]);
                    mma16816(acc[mt][1][1], af[cb][mt], &bf[cb][1][2]);
                }
            }
        }
    }

    // ---------------- epilogue ----------------
    if (EPI == 0) {
        #pragma unroll
        for (int bt = 0; bt < 2; bt++) if (bt ? hb1 : hb0) {
            int lb = wn + 4 * bt;
            int nb = bn + 16 * lb + 2 * tig;
            float bi = bias[nb], bff = bias[nb + 1], bg = bias[nb + 8], bo = bias[nb + 9];
            int u = (bn >> 2) + 4 * lb + tig;
            #pragma unroll
            for (int mt = 0; mt < 2; mt++) {
                #pragma unroll
                for (int hr = 0; hr < 2; hr++) {
                    int b = bm + wm * 32 + mt * 16 + g8 + hr * 8;
                    int d = hr * 2;
                    float ig = acc[mt][bt][0][d]     + bi;
                    float fg = acc[mt][bt][0][d + 1] + bff;
                    float gg = acc[mt][bt][1][d]     + bg;
                    float og = acc[mt][bt][1][d + 1] + bo;
                    size_t ci = (size_t)b * HID + u;
                    float cn = sigf(fg) * cptr[ci] + sigf(ig) * tanhe(gg);
                    float hn = sigf(og) * tanhe(cn);
                    cptr[ci] = cn;
                    hptr[ci] = __float2half(hn);
                    if (yptr) yptr[ci] = hn;
                }
            }
        }
    } else {
        #pragma unroll
        for (int bt = 0; bt < 2; bt++) if (bt ? hb1 : hb0) {
            int lb = wn + 4 * bt;
            #pragma unroll
            for (int mt = 0; mt < 2; mt++) {
                int r0 = bm + wm * 32 + mt * 16 + g8;
                #pragma unroll
                for (int q = 0; q < 2; q++) {
                    int col = bn + 16 * lb + 8 * q + 2 * tig;
                    float b0 = bias[col], b1 = bias[col + 1];
                    int l2 = col >> 10, j = col & (HID - 1);
                    __half2 v0 = __floats2half2_rn(tanhe(acc[mt][bt][q][0] + b0),
                                                   tanhe(acc[mt][bt][q][1] + b1));
                    __half2 v1 = __floats2half2_rn(tanhe(acc[mt][bt][q][2] + b0),
                                                   tanhe(acc[mt][bt][q][3] + b1));
                    size_t lofs = (size_t)l2 * 2 * BAT * HID;   // ping buffer 0
                    *(__half2*)(hptr + lofs + (size_t)r0 * HID + j)       = v0;
                    *(__half2*)(hptr + lofs + (size_t)(r0 + 8) * HID + j) = v1;
                }
            }
        }
    }
}

// ---------------- launch ----------------
extern "C" void kernel_launch(void* const* d_in, const int* in_sizes, int n_in,
                              void* d_out, int out_size)
{
    const float* z   = (const float*)d_in[0];
    const float* thW = (const float*)d_in[1];
    const float* thb = (const float*)d_in[2];
    const float* emb = (const float*)d_in[3];
    const float* Wih = (const float*)d_in[4];
    const float* Whh = (const float*)d_in[5];
    const float* bih = (const float*)d_in[6];
    const float* bhh = (const float*)d_in[7];
    float* out = (float*)d_out;

    __half *Wc, *thWc, *z16, *x0, *h;
    float *c, *biasc;
    cudaGetSymbolAddress((void**)&Wc,    g_Wc);
    cudaGetSymbolAddress((void**)&thWc,  g_thW);
    cudaGetSymbolAddress((void**)&z16,   g_z16);
    cudaGetSymbolAddress((void**)&x0,    g_x0);
    cudaGetSymbolAddress((void**)&h,     g_h);
    cudaGetSymbolAddress((void**)&c,     g_c);
    cudaGetSymbolAddress((void**)&biasc, g_biasc);

    cudaFuncSetAttribute(lstm_gemm<0>, cudaFuncAttributeMaxDynamicSharedMemorySize, SMEM_BYTES);
    cudaFuncSetAttribute(lstm_gemm<1>, cudaFuncAttributeMaxDynamicSharedMemorySize, SMEM_BYTES);

    auto hb = [&](int l, int p) { return h + ((size_t)l * 2 + p) * BAT * HID; };

    convert_w_kernel<<<1024, 256>>>(Wih, Whh);
    convert_misc_kernel<<<1024, 256>>>(z, thW, emb, bih, bhh);

    // h0 = tanh(z @ to_h_W^T + to_h_b): M=512, N=2048, K=1024 -> ping buffer 0
    // 19 column tiles (18 x 112 + 1 x 32)
    lstm_gemm<1><<<dim3(19, 4), 512, SMEM_BYTES>>>(z16, z16, thWc, thb,
                                                   nullptr, h, nullptr, 16, 2 * HID);

    for (int t = 0; t < TT; t++) {
        int p = t & 1;
        for (int l = 0; l < NL; l++) {
            const __half* Ain  = (l == 0) ? (t == 0 ? x0 : hb(1, p)) : hb(0, p ^ 1);
            const __half* Arec = hb(l, p);
            // 37 column tiles (36 x 112 + 1 x 64) x 4 M rows = 148 CTAs
            lstm_gemm<0><<<dim3(37, 4), 512, SMEM_BYTES>>>(
                Ain, Arec,
                Wc + (size_t)l * 4 * HID * 2 * HID,
                biasc + l * 4 * HID,
                c + (size_t)l * BAT * HID,
                hb(l, p ^ 1),
                (l == NL - 1) ? out + (size_t)t * BAT * HID : nullptr,
                32, 4 * HID);
        }
    }
}

// round 12
// speedup vs baseline: 1.0048x; 1.0048x over previous
#include <cuda_runtime.h>
#include <cuda_fp16.h>
#include <cstdint>
#include <cstddef>

#define HID 1024
#define BAT 512
#define NL  2
#define TT  32

#define A_BYTES   8192           // 64 rows x 64 halves
#define B_BYTES   16384          // 128 rows x 64 halves
#define STG_BYTES (A_BYTES + B_BYTES)   // 24576
#define NSTG 4
#define SMEM_BYTES (NSTG * STG_BYTES)   // 98304 -> 2 CTAs/SM

// ---------------- device scratch ----------------
__device__ __half g_Wc[(size_t)NL * 4 * HID * 2 * HID];  // [l][np][k] gate-interleaved, K-concat
__device__ __half g_thW[(size_t)2 * HID * HID];
__device__ float  g_biasc[NL * 4 * HID];
__device__ __half g_z16[(size_t)BAT * HID];
__device__ __half g_x0[(size_t)BAT * HID];
__device__ __half g_h[NL * 2][(size_t)BAT * HID];        // ping-pong per layer
__device__ float  g_c[NL][(size_t)BAT * HID];

// ---------------- helpers ----------------
__device__ __forceinline__ uint32_t smem_u32(const void* p) {
    return (uint32_t)__cvta_generic_to_shared(p);
}
__device__ __forceinline__ void cp16(uint32_t s, const void* g) {
    asm volatile("cp.async.cg.shared.global [%0], [%1], 16;\n" :: "r"(s), "l"(g));
}
__device__ __forceinline__ void mma16816(float* d, const uint32_t* a, const uint32_t* b) {
    asm volatile(
        "mma.sync.aligned.m16n8k16.row.col.f32.f16.f16.f32 "
        "{%0,%1,%2,%3}, {%4,%5,%6,%7}, {%8,%9}, {%0,%1,%2,%3};\n"
        : "+f"(d[0]), "+f"(d[1]), "+f"(d[2]), "+f"(d[3])
        : "r"(a[0]), "r"(a[1]), "r"(a[2]), "r"(a[3]), "r"(b[0]), "r"(b[1]));
}
#define LDSM4(r, addr)                                                          \
    asm volatile("ldmatrix.sync.aligned.m8n8.x4.shared.b16 {%0,%1,%2,%3}, [%4];"\
        : "=r"((r)[0]), "=r"((r)[1]), "=r"((r)[2]), "=r"((r)[3]) : "r"(addr))

// smem tile rows of 64 halves (128B), classic 8-chunk xor swizzle
__device__ __forceinline__ int swz64(int r, int k) {
    return r * 64 + ((((k >> 3) ^ (r & 7)) << 3) | (k & 7));
}

__device__ __forceinline__ float sigf(float x) {
    return __fdividef(1.f, 1.f + __expf(-x));
}
__device__ __forceinline__ float tanhe(float x) {
    return __fdividef(2.f, 1.f + __expf(-2.f * x)) - 1.f;
}

// ---------------- conversion kernels ----------------
// gate-interleaved: np = 16*(u>>2) + 2*(u&3) + gofs, gofs = {i:0, f:1, g:8, o:9}
__global__ void convert_w_kernel(const float* __restrict__ Wih, const float* __restrict__ Whh) {
    size_t total = (size_t)NL * 4 * HID * 2 * HID;
    for (size_t idx = (size_t)blockIdx.x * blockDim.x + threadIdx.x; idx < total;
         idx += (size_t)gridDim.x * blockDim.x) {
        int k  = (int)(idx & (2 * HID - 1));
        int np = (int)((idx >> 11) & 4095);
        int l  = (int)(idx >> 23);
        int within = np & 15, block = np >> 4;
        int gate = ((within & 8) ? 2 : 0) + (within & 1);
        int tig  = (within & 7) >> 1;
        int u = block * 4 + tig;
        size_t ln = (size_t)l * 4 * HID + (size_t)gate * HID + u;
        float v = (k < HID) ? Wih[ln * HID + k] : Whh[ln * HID + (k - HID)];
        g_Wc[idx] = __float2half(v);
    }
}
__global__ void convert_misc_kernel(const float* __restrict__ z, const float* __restrict__ thW,
                                    const float* __restrict__ emb,
                                    const float* __restrict__ bih, const float* __restrict__ bhh) {
    int total = 2 * HID * HID;
    for (int idx = blockIdx.x * blockDim.x + threadIdx.x; idx < total;
         idx += gridDim.x * blockDim.x) {
        g_thW[idx] = __float2half(thW[idx]);
        if (idx < BAT * HID) {
            g_z16[idx] = __float2half(z[idx]);
            g_x0[idx]  = __float2half(emb[idx & (HID - 1)]);
        }
        if (idx < NL * BAT * HID) ((float*)g_c)[idx] = 0.f;
        if (idx < NL * 4 * HID) {
            int l = idx >> 12, np = idx & 4095;
            int within = np & 15, block = np >> 4;
            int gate = ((within & 8) ? 2 : 0) + (within & 1);
            int tig  = (within & 7) >> 1;
            int u = block * 4 + tig;
            int src = l * 4 * HID + gate * HID + u;
            g_biasc[idx] = bih[src] + bhh[src];
        }
    }
}

// ---------------- fused GEMM (+LSTM cell), 2 CTAs/SM ----------------
// C[512,N] = [A0|A1][512,K] @ Bw[N,K]^T
// CTA tile 64x128, 8 warps (2m x 4n), warp tile 32x32 (same as R6 per-warp).
// 4-stage cp.async ring (96KB -> 2 CTAs/SM), per-k-tile barrier,
// in-tile register double-buffered fragments with XOR slice addressing.
template<int EPI>
__global__ void __launch_bounds__(256, 2)
lstm_gemm(const __half* __restrict__ A0, const __half* __restrict__ A1,
          const __half* __restrict__ Bw, const float* __restrict__ bias,
          float* __restrict__ cptr, __half* __restrict__ hptr,
          float* __restrict__ yptr, int KT)            // KT in 64-half k-tiles
{
    extern __shared__ __half sm[];
    const uint32_t sb = smem_u32(sm);
    const int tid = threadIdx.x, wid = tid >> 5, lane = tid & 31;
    const int g8 = lane >> 2, tig = lane & 3;
    const int wm = wid & 1, wn = wid >> 1;             // 2m x 4n, warp tile 32x32
    const int bm = blockIdx.y * 64, bn = blockIdx.x * 128;
    const int Kh = KT * 64;

    float acc[2][4][4];
    #pragma unroll
    for (int a = 0; a < 2; a++)
        #pragma unroll
        for (int b = 0; b < 4; b++)
            #pragma unroll
            for (int d = 0; d < 4; d++) acc[a][b][d] = 0.f;

    // slice-0 tile-relative byte offsets; slice s: off ^ (s<<5)
    uint32_t aoff[2], boff[2];
    {
        int arow = lane & 15, ac = (lane >> 4) << 3;
        int brow = (lane & 7) + ((lane & 16) >> 1), bc = lane & 8;
        #pragma unroll
        for (int mt = 0; mt < 2; mt++)
            aoff[mt] = 2 * swz64(wm * 32 + mt * 16 + arow, ac);
        #pragma unroll
        for (int p = 0; p < 2; p++)
            boff[p] = A_BYTES + 2 * swz64(wn * 32 + p * 16 + brow, bc);
    }

    auto fill = [&](int kt) {
        int st = kt & (NSTG - 1);
        int k0 = kt << 6;
        const __half* Ap; int ks;
        if (k0 < HID) { Ap = A0; ks = k0; } else { Ap = A1; ks = k0 - HID; }
        uint32_t ab = sb + st * STG_BYTES, bb = ab + A_BYTES;
        int r0 = tid >> 3, c = tid & 7;
        #pragma unroll
        for (int i = 0; i < 2; i++) {                  // A: 64 rows
            int r = r0 + i * 32;
            cp16(ab + 2 * swz64(r, c << 3), Ap + (size_t)(bm + r) * HID + ks + (c << 3));
        }
        #pragma unroll
        for (int i = 0; i < 4; i++) {                  // B: 128 rows
            int r = r0 + i * 32;
            cp16(bb + 2 * swz64(r, c << 3), Bw + (size_t)(bn + r) * Kh + k0 + (c << 3));
        }
    };

    fill(0); asm volatile("cp.async.commit_group;\n");
    if (KT > 1) { fill(1); asm volatile("cp.async.commit_group;\n"); }
    if (KT > 2) { fill(2); asm volatile("cp.async.commit_group;\n"); }

    for (int i = 0; i < KT; i++) {
        if (i + 3 <= KT)      asm volatile("cp.async.wait_group 2;\n");
        else if (i + 2 == KT) asm volatile("cp.async.wait_group 1;\n");
        else                  asm volatile("cp.async.wait_group 0;\n");
        __syncthreads();
        if (i + 3 < KT) { fill(i + 3); asm volatile("cp.async.commit_group;\n"); }

        const uint32_t tb = sb + (i & (NSTG - 1)) * STG_BYTES;

        uint32_t af[2][2][4], bf[2][2][4];
        #pragma unroll
        for (int mt = 0; mt < 2; mt++) LDSM4(af[0][mt], tb + aoff[mt]);
        #pragma unroll
        for (int p = 0; p < 2; p++)    LDSM4(bf[0][p],  tb + boff[p]);

        #pragma unroll
        for (int s = 0; s < 4; s++) {
            const int cb = s & 1, nb = cb ^ 1;
            if (s < 3) {
                const uint32_t x = (uint32_t)(s + 1) << 5;
                #pragma unroll
                for (int mt = 0; mt < 2; mt++) LDSM4(af[nb][mt], tb + (aoff[mt] ^ x));
                #pragma unroll
                for (int p = 0; p < 2; p++)    LDSM4(bf[nb][p],  tb + (boff[p] ^ x));
            }
            #pragma unroll
            for (int mt = 0; mt < 2; mt++) {
                #pragma unroll
                for (int p = 0; p < 2; p++) {
                    mma16816(acc[mt][2 * p],     af[cb][mt], &bf[cb][p][0]);
                    mma16816(acc[mt][2 * p + 1], af[cb][mt], &bf[cb][p][2]);
                }
            }
        }
    }

    // ---------------- epilogue ----------------
    if (EPI == 0) {
        #pragma unroll
        for (int p = 0; p < 2; p++) {
            int nb = bn + wn * 32 + p * 16 + 2 * tig;
            float bi = bias[nb], bff = bias[nb + 1], bg = bias[nb + 8], bo = bias[nb + 9];
            int u = (bn >> 2) + wn * 8 + p * 4 + tig;
            #pragma unroll
            for (int mt = 0; mt < 2; mt++) {
                #pragma unroll
                for (int hr = 0; hr < 2; hr++) {
                    int b = bm + wm * 32 + mt * 16 + g8 + hr * 8;
                    int d = hr * 2;
                    float ig = acc[mt][2 * p][d]         + bi;
                    float fg = acc[mt][2 * p][d + 1]     + bff;
                    float gg = acc[mt][2 * p + 1][d]     + bg;
                    float og = acc[mt][2 * p + 1][d + 1] + bo;
                    size_t ci = (size_t)b * HID + u;
                    float cn = sigf(fg) * cptr[ci] + sigf(ig) * tanhe(gg);
                    float hn = sigf(og) * tanhe(cn);
                    cptr[ci] = cn;
                    hptr[ci] = __float2half(hn);
                    if (yptr) yptr[ci] = hn;
                }
            }
        }
    } else {
        #pragma unroll
        for (int mt = 0; mt < 2; mt++) {
            int r0 = bm + wm * 32 + mt * 16 + g8;
            #pragma unroll
            for (int nt = 0; nt < 4; nt++) {
                int col = bn + wn * 32 + nt * 8 + 2 * tig;
                float b0 = bias[col], b1 = bias[col + 1];
                int l2 = col >> 10, j = col & (HID - 1);
                __half2 v0 = __floats2half2_rn(tanhe(acc[mt][nt][0] + b0),
                                               tanhe(acc[mt][nt][1] + b1));
                __half2 v1 = __floats2half2_rn(tanhe(acc[mt][nt][2] + b0),
                                               tanhe(acc[mt][nt][3] + b1));
                size_t lofs = (size_t)l2 * 2 * BAT * HID;   // ping buffer 0 of layer l2
                *(__half2*)(hptr + lofs + (size_t)r0 * HID + j)       = v0;
                *(__half2*)(hptr + lofs + (size_t)(r0 + 8) * HID + j) = v1;
            }
        }
    }
}

// ---------------- launch ----------------
extern "C" void kernel_launch(void* const* d_in, const int* in_sizes, int n_in,
                              void* d_out, int out_size)
{
    const float* z   = (const float*)d_in[0];
    const float* thW = (const float*)d_in[1];
    const float* thb = (const float*)d_in[2];
    const float* emb = (const float*)d_in[3];
    const float* Wih = (const float*)d_in[4];
    const float* Whh = (const float*)d_in[5];
    const float* bih = (const float*)d_in[6];
    const float* bhh = (const float*)d_in[7];
    float* out = (float*)d_out;

    __half *Wc, *thWc, *z16, *x0, *h;
    float *c, *biasc;
    cudaGetSymbolAddress((void**)&Wc,    g_Wc);
    cudaGetSymbolAddress((void**)&thWc,  g_thW);
    cudaGetSymbolAddress((void**)&z16,   g_z16);
    cudaGetSymbolAddress((void**)&x0,    g_x0);
    cudaGetSymbolAddress((void**)&h,     g_h);
    cudaGetSymbolAddress((void**)&c,     g_c);
    cudaGetSymbolAddress((void**)&biasc, g_biasc);

    cudaFuncSetAttribute(lstm_gemm<0>, cudaFuncAttributeMaxDynamicSharedMemorySize, SMEM_BYTES);
    cudaFuncSetAttribute(lstm_gemm<1>, cudaFuncAttributeMaxDynamicSharedMemorySize, SMEM_BYTES);

    auto hb = [&](int l, int p) { return h + ((size_t)l * 2 + p) * BAT * HID; };

    convert_w_kernel<<<1024, 256>>>(Wih, Whh);
    convert_misc_kernel<<<1024, 256>>>(z, thW, emb, bih, bhh);

    // h0 = tanh(z @ to_h_W^T + to_h_b): M=512, N=2048, K=1024 -> ping buffer 0
    lstm_gemm<1><<<dim3(16, 8), 256, SMEM_BYTES>>>(z16, z16, thWc, thb,
                                                   nullptr, h, nullptr, 16);

    for (int t = 0; t < TT; t++) {
        int p = t & 1;
        for (int l = 0; l < NL; l++) {
            const __half* Ain  = (l == 0) ? (t == 0 ? x0 : hb(1, p)) : hb(0, p ^ 1);
            const __half* Arec = hb(l, p);
            lstm_gemm<0><<<dim3(32, 8), 256, SMEM_BYTES>>>(
                Ain, Arec,
                Wc + (size_t)l * 4 * HID * 2 * HID,
                biasc + l * 4 * HID,
                c + (size_t)l * BAT * HID,
                hb(l, p ^ 1),
                (l == NL - 1) ? out + (size_t)t * BAT * HID : nullptr,
                32);
        }
    }
}

// round 13
// speedup vs baseline: 1.0972x; 1.0920x over previous
#include <cuda_runtime.h>
#include <cuda_fp16.h>
#include <cstdint>
#include <cstddef>

#define HID 1024
#define BAT 512
#define NL  2
#define TT  32

#define A_BYTES   16384          // 128 rows x 64 halves
#define STG_BYTES 32768          // A + B
#define NSTG 6
#define SMEM_BYTES (NSTG * STG_BYTES)   // 196608, 1 CTA/SM

// ---------------- device scratch ----------------
__device__ __half g_Wc[(size_t)NL * 4 * HID * 2 * HID];  // [l][np][k] gate-interleaved, K-concat
__device__ __half g_thW[(size_t)2 * HID * HID];
__device__ float  g_biasc[NL * 4 * HID];
__device__ __half g_z16[(size_t)BAT * HID];
__device__ __half g_x0[(size_t)BAT * HID];
__device__ __half g_h[NL * 2][(size_t)BAT * HID];        // ping-pong per layer
__device__ float  g_c[NL][(size_t)BAT * HID];
__device__ unsigned g_cnt;                               // grid barrier (cumulative)
__device__ unsigned g_gen;                               // grid barrier generation

// ---------------- helpers ----------------
__device__ __forceinline__ uint32_t smem_u32(const void* p) {
    return (uint32_t)__cvta_generic_to_shared(p);
}
__device__ __forceinline__ void cp16(uint32_t s, const void* g) {
    asm volatile("cp.async.cg.shared.global [%0], [%1], 16;\n" :: "r"(s), "l"(g));
}
__device__ __forceinline__ void mma16816(float* d, const uint32_t* a, const uint32_t* b) {
    asm volatile(
        "mma.sync.aligned.m16n8k16.row.col.f32.f16.f16.f32 "
        "{%0,%1,%2,%3}, {%4,%5,%6,%7}, {%8,%9}, {%0,%1,%2,%3};\n"
        : "+f"(d[0]), "+f"(d[1]), "+f"(d[2]), "+f"(d[3])
        : "r"(a[0]), "r"(a[1]), "r"(a[2]), "r"(a[3]), "r"(b[0]), "r"(b[1]));
}
#define LDSM4(r, addr)                                                          \
    asm volatile("ldmatrix.sync.aligned.m8n8.x4.shared.b16 {%0,%1,%2,%3}, [%4];"\
        : "=r"((r)[0]), "=r"((r)[1]), "=r"((r)[2]), "=r"((r)[3]) : "r"(addr))

__device__ __forceinline__ int swz64(int r, int k) {
    return r * 64 + ((((k >> 3) ^ (r & 7)) << 3) | (k & 7));
}
__device__ __forceinline__ float sigf(float x) {
    return __fdividef(1.f, 1.f + __expf(-x));
}
__device__ __forceinline__ float tanhe(float x) {
    return __fdividef(2.f, 1.f + __expf(-2.f * x)) - 1.f;
}

__device__ __forceinline__ void grid_sync(unsigned target) {
    __syncthreads();
    if (threadIdx.x == 0) {
        __threadfence();
        unsigned arr = atomicAdd(&g_cnt, 1u) + 1u;
        if (arr == gridDim.x * target) atomicExch(&g_gen, target);
        while (*(volatile unsigned*)&g_gen < target) { }
        __threadfence();
    }
    __syncthreads();
}

// ---------------- conversion kernels ----------------
// gate-interleaved: np = 16*(u>>2) + 2*(u&3) + gofs, gofs = {i:0, f:1, g:8, o:9}
__global__ void convert_w_kernel(const float* __restrict__ Wih, const float* __restrict__ Whh) {
    size_t total = (size_t)NL * 4 * HID * 2 * HID;
    for (size_t idx = (size_t)blockIdx.x * blockDim.x + threadIdx.x; idx < total;
         idx += (size_t)gridDim.x * blockDim.x) {
        int k  = (int)(idx & (2 * HID - 1));
        int np = (int)((idx >> 11) & 4095);
        int l  = (int)(idx >> 23);
        int within = np & 15, block = np >> 4;
        int gate = ((within & 8) ? 2 : 0) + (within & 1);
        int tig  = (within & 7) >> 1;
        int u = block * 4 + tig;
        size_t ln = (size_t)l * 4 * HID + (size_t)gate * HID + u;
        float v = (k < HID) ? Wih[ln * HID + k] : Whh[ln * HID + (k - HID)];
        g_Wc[idx] = __float2half(v);
    }
}
__global__ void convert_misc_kernel(const float* __restrict__ z, const float* __restrict__ thW,
                                    const float* __restrict__ emb,
                                    const float* __restrict__ bih, const float* __restrict__ bhh) {
    if (blockIdx.x == 0 && threadIdx.x == 0) { g_cnt = 0u; g_gen = 0u; }
    int total = 2 * HID * HID;
    for (int idx = blockIdx.x * blockDim.x + threadIdx.x; idx < total;
         idx += gridDim.x * blockDim.x) {
        g_thW[idx] = __float2half(thW[idx]);
        if (idx < BAT * HID) {
            g_z16[idx] = __float2half(z[idx]);
            g_x0[idx]  = __float2half(emb[idx & (HID - 1)]);
        }
        if (idx < NL * BAT * HID) ((float*)g_c)[idx] = 0.f;
        if (idx < NL * 4 * HID) {
            int l = idx >> 12, np = idx & 4095;
            int within = np & 15, block = np >> 4;
            int gate = ((within & 8) ? 2 : 0) + (within & 1);
            int tig  = (within & 7) >> 1;
            int u = block * 4 + tig;
            int src = l * 4 * HID + gate * HID + u;
            g_biasc[idx] = bih[src] + bhh[src];
        }
    }
}

// ---------------- one GEMM stage (R6 body), device function ----------------
// CTA tile 128x128, 16 warps (4m x 4n), warp tile 32x32, 6-stage cp.async ring,
// one barrier per PAIR of 64-half k-tiles, register double-buffered fragments,
// XOR slice addressing. If PREF, B of ring slots 0-3 was prefetched pre-entry.
// At the end, prefetch next stage's B (k-tiles 0..3), uncommitted.
template<int EPI, bool PREF>
__device__ __forceinline__ void gemm_stage(
    const __half* __restrict__ A0, const __half* __restrict__ A1,
    const __half* __restrict__ Bw, const float* __restrict__ bias,
    float* __restrict__ cptr, __half* __restrict__ hptr, float* __restrict__ yptr,
    const int KT, const int bm, const int bn, const uint32_t sb,
    const uint32_t aoff0, const uint32_t aoff1,
    const uint32_t boff0, const uint32_t boff1,
    const int wm, const int wn, const int g8, const int tig, const int tid,
    const __half* nextBw, const int nextBn)
{
    const int Kh = KT * 64;
    const int NP = KT >> 1;

    float acc[2][4][4];
    #pragma unroll
    for (int a = 0; a < 2; a++)
        #pragma unroll
        for (int b = 0; b < 4; b++)
            #pragma unroll
            for (int d = 0; d < 4; d++) acc[a][b][d] = 0.f;

    auto fillA = [&](int kt) {
        int st = kt % NSTG;
        int k0 = kt << 6;
        const __half* Ap; int ks;
        if (k0 < HID) { Ap = A0; ks = k0; } else { Ap = A1; ks = k0 - HID; }
        uint32_t ab = sb + st * STG_BYTES;
        #pragma unroll
        for (int i = 0; i < 2; i++) {
            int idx = tid + i * 512;
            int r = idx >> 3, cc = idx & 7;
            cp16(ab + 2 * swz64(r, cc << 3), Ap + (size_t)(bm + r) * HID + ks + (cc << 3));
        }
    };
    auto fillB = [&](int kt) {
        int st = kt % NSTG;
        int k0 = kt << 6;
        uint32_t bb = sb + st * STG_BYTES + A_BYTES;
        #pragma unroll
        for (int i = 0; i < 2; i++) {
            int idx = tid + i * 512;
            int r = idx >> 3, cc = idx & 7;
            cp16(bb + 2 * swz64(r, cc << 3), Bw + (size_t)(bn + r) * Kh + k0 + (cc << 3));
        }
    };

    if (PREF) {           // B 0..3 already in ring (pre-barrier prefetch)
        fillA(0); fillA(1); asm volatile("cp.async.commit_group;\n");
        fillA(2); fillA(3); asm volatile("cp.async.commit_group;\n");
    } else {
        fillA(0); fillB(0); fillA(1); fillB(1); asm volatile("cp.async.commit_group;\n");
        fillA(2); fillB(2); fillA(3); fillB(3); asm volatile("cp.async.commit_group;\n");
    }

    for (int i = 0; i < NP; i++) {
        if (i + 1 < NP) asm volatile("cp.async.wait_group 1;\n");
        else            asm volatile("cp.async.wait_group 0;\n");
        __syncthreads();
        if (i + 2 < NP) {
            fillA(2 * i + 4); fillB(2 * i + 4);
            fillA(2 * i + 5); fillB(2 * i + 5);
            asm volatile("cp.async.commit_group;\n");
        }

        const uint32_t base0 = sb + ((2 * i) % NSTG) * STG_BYTES;
        const uint32_t base1 = sb + ((2 * i + 1) % NSTG) * STG_BYTES;

        uint32_t af[2][2][4], bf[2][2][4];
        LDSM4(af[0][0], base0 + aoff0);
        LDSM4(af[0][1], base0 + aoff1);
        LDSM4(bf[0][0], base0 + boff0);
        LDSM4(bf[0][1], base0 + boff1);

        #pragma unroll
        for (int ss = 0; ss < 8; ss++) {
            const int cb = ss & 1, nb = cb ^ 1;
            if (ss < 7) {
                const int ns = ss + 1;
                const uint32_t nbase = (ns < 4) ? base0 : base1;
                const uint32_t x = (uint32_t)(ns & 3) << 5;
                LDSM4(af[nb][0], nbase + (aoff0 ^ x));
                LDSM4(af[nb][1], nbase + (aoff1 ^ x));
                LDSM4(bf[nb][0], nbase + (boff0 ^ x));
                LDSM4(bf[nb][1], nbase + (boff1 ^ x));
            }
            #pragma unroll
            for (int mt = 0; mt < 2; mt++) {
                #pragma unroll
                for (int p = 0; p < 2; p++) {
                    mma16816(acc[mt][2 * p],     af[cb][mt], &bf[cb][p][0]);
                    mma16816(acc[mt][2 * p + 1], af[cb][mt], &bf[cb][p][2]);
                }
            }
        }
    }

    // prefetch next stage's B into ring slots 0..3 (uncommitted; safe after sync)
    __syncthreads();
    if (nextBw) {
        #pragma unroll
        for (int kt = 0; kt < 4; kt++) {
            uint32_t bb = sb + kt * STG_BYTES + A_BYTES;
            #pragma unroll
            for (int i2 = 0; i2 < 2; i2++) {
                int idx = tid + i2 * 512;
                int r = idx >> 3, cc = idx & 7;
                cp16(bb + 2 * swz64(r, cc << 3),
                     nextBw + (size_t)(nextBn + r) * (2 * HID) + (kt << 6) + (cc << 3));
            }
        }
    }

    // ---------------- epilogue ----------------
    if (EPI == 0) {
        #pragma unroll
        for (int p = 0; p < 2; p++) {
            int nb = bn + wn * 32 + p * 16 + 2 * tig;
            float bi = bias[nb], bff = bias[nb + 1], bg = bias[nb + 8], bo = bias[nb + 9];
            int u = (bn >> 2) + wn * 8 + p * 4 + tig;
            #pragma unroll
            for (int mt = 0; mt < 2; mt++) {
                #pragma unroll
                for (int hr = 0; hr < 2; hr++) {
                    int b = bm + wm * 32 + mt * 16 + g8 + hr * 8;
                    int d = hr * 2;
                    float ig = acc[mt][2 * p][d]         + bi;
                    float fg = acc[mt][2 * p][d + 1]     + bff;
                    float gg = acc[mt][2 * p + 1][d]     + bg;
                    float og = acc[mt][2 * p + 1][d + 1] + bo;
                    size_t ci = (size_t)b * HID + u;
                    float cn = sigf(fg) * cptr[ci] + sigf(ig) * tanhe(gg);
                    float hn = sigf(og) * tanhe(cn);
                    cptr[ci] = cn;
                    hptr[ci] = __float2half(hn);
                    if (yptr) yptr[ci] = hn;
                }
            }
        }
    } else {
        #pragma unroll
        for (int mt = 0; mt < 2; mt++) {
            int r0 = bm + wm * 32 + mt * 16 + g8;
            #pragma unroll
            for (int nt = 0; nt < 4; nt++) {
                int col = bn + wn * 32 + nt * 8 + 2 * tig;
                float b0 = bias[col], b1 = bias[col + 1];
                int l2 = col >> 10, j = col & (HID - 1);
                __half2 v0 = __floats2half2_rn(tanhe(acc[mt][nt][0] + b0),
                                               tanhe(acc[mt][nt][1] + b1));
                __half2 v1 = __floats2half2_rn(tanhe(acc[mt][nt][2] + b0),
                                               tanhe(acc[mt][nt][3] + b1));
                size_t lofs = (size_t)l2 * 2 * BAT * HID;   // ping buffer 0 of layer l2
                *(__half2*)(hptr + lofs + (size_t)r0 * HID + j)       = v0;
                *(__half2*)(hptr + lofs + (size_t)(r0 + 8) * HID + j) = v1;
            }
        }
    }
}

// ---------------- persistent kernel: init + 64 stages, grid-synced ----------
__global__ void __launch_bounds__(512)
lstm_persist(const __half* __restrict__ z16v, const __half* __restrict__ thWc,
             const float* __restrict__ thb, const __half* __restrict__ x0v,
             const __half* __restrict__ Wc, const float* __restrict__ biasc,
             float* __restrict__ c, __half* __restrict__ h,
             float* __restrict__ out)
{
    extern __shared__ __half sm[];
    const uint32_t sb = smem_u32(sm);
    const int tid = threadIdx.x, wid = tid >> 5, lane = tid & 31;
    const int g8 = lane >> 2, tig = lane & 3;
    const int wm = wid & 3, wn = wid >> 2;
    const int cta = blockIdx.x;

    uint32_t aoff0, aoff1, boff0, boff1;
    {
        int arow = lane & 15, ac = (lane >> 4) << 3;
        int brow = (lane & 7) + ((lane & 16) >> 1), bc = lane & 8;
        aoff0 = 2 * swz64(wm * 32 + arow, ac);
        aoff1 = 2 * swz64(wm * 32 + 16 + arow, ac);
        boff0 = A_BYTES + 2 * swz64(wn * 32 + brow, bc);
        boff1 = A_BYTES + 2 * swz64(wn * 32 + 16 + brow, bc);
    }

    const int sbx = cta & 31, sby = cta >> 5;   // stage-GEMM tile (32 x 4)
    const int nbn0 = sbx * 128;

    // ---- init GEMM (64 CTAs) / others just prefetch stage-0 B ----
    if (cta < 64) {
        int bx = cta & 15, by = cta >> 4;
        gemm_stage<1, false>(z16v, z16v, thWc, thb, nullptr, h, nullptr,
                             16, by * 128, bx * 128, sb,
                             aoff0, aoff1, boff0, boff1,
                             wm, wn, g8, tig, tid,
                             Wc, nbn0);
    } else {
        #pragma unroll
        for (int kt = 0; kt < 4; kt++) {
            uint32_t bb = sb + kt * STG_BYTES + A_BYTES;
            #pragma unroll
            for (int i2 = 0; i2 < 2; i2++) {
                int idx = tid + i2 * 512;
                int r = idx >> 3, cc = idx & 7;
                cp16(bb + 2 * swz64(r, cc << 3),
                     Wc + (size_t)(nbn0 + r) * (2 * HID) + (kt << 6) + (cc << 3));
            }
        }
    }
    grid_sync(1u);

    #pragma unroll 1
    for (int s = 0; s < 64; s++) {
        const int t = s >> 1, l = s & 1, p = t & 1;
        const __half* Ain = (l == 0)
            ? (t == 0 ? x0v : h + (size_t)(2 + p) * (BAT * HID))
            : h + (size_t)(p ^ 1) * (BAT * HID);
        const __half* Arec = h + (size_t)(l * 2 + p) * (BAT * HID);
        const __half* Bs = Wc + (size_t)l * (4 * HID * 2 * HID);
        const __half* nB = (s + 1 < 64)
            ? Wc + (size_t)((s + 1) & 1) * (4 * HID * 2 * HID) : nullptr;
        gemm_stage<0, true>(Ain, Arec, Bs, biasc + l * 4 * HID,
                            c + (size_t)l * BAT * HID,
                            h + (size_t)(l * 2 + (p ^ 1)) * (BAT * HID),
                            (l == 1) ? out + (size_t)t * BAT * HID : nullptr,
                            32, sby * 128, sbx * 128, sb,
                            aoff0, aoff1, boff0, boff1,
                            wm, wn, g8, tig, tid,
                            nB, nbn0);
        if (s < 63) grid_sync((unsigned)(s + 2));
    }
}

// ---------------- launch ----------------
extern "C" void kernel_launch(void* const* d_in, const int* in_sizes, int n_in,
                              void* d_out, int out_size)
{
    const float* z   = (const float*)d_in[0];
    const float* thW = (const float*)d_in[1];
    const float* thb = (const float*)d_in[2];
    const float* emb = (const float*)d_in[3];
    const float* Wih = (const float*)d_in[4];
    const float* Whh = (const float*)d_in[5];
    const float* bih = (const float*)d_in[6];
    const float* bhh = (const float*)d_in[7];
    float* out = (float*)d_out;

    __half *Wc, *thWc, *z16, *x0, *h;
    float *c, *biasc;
    cudaGetSymbolAddress((void**)&Wc,    g_Wc);
    cudaGetSymbolAddress((void**)&thWc,  g_thW);
    cudaGetSymbolAddress((void**)&z16,   g_z16);
    cudaGetSymbolAddress((void**)&x0,    g_x0);
    cudaGetSymbolAddress((void**)&h,     g_h);
    cudaGetSymbolAddress((void**)&c,     g_c);
    cudaGetSymbolAddress((void**)&biasc, g_biasc);

    cudaFuncSetAttribute(lstm_persist, cudaFuncAttributeMaxDynamicSharedMemorySize, SMEM_BYTES);

    convert_w_kernel<<<1024, 256>>>(Wih, Whh);
    convert_misc_kernel<<<1024, 256>>>(z, thW, emb, bih, bhh);

    lstm_persist<<<128, 512, SMEM_BYTES>>>(z16, thWc, thb, x0, Wc, biasc, c, h, out);
}

// round 16
// speedup vs baseline: 1.1202x; 1.0210x over previous
#include <cuda_runtime.h>
#include <cuda_fp16.h>
#include <cstdint>
#include <cstddef>

#define HID 1024
#define BAT 512
#define NL  2
#define TT  32

#define A_BYTES   16384          // 128 rows x 64 halves
#define STG_BYTES 32768          // A + B
#define NSTG 6
#define SMEM_BYTES (NSTG * STG_BYTES)   // 196608, 1 CTA/SM

// ---------------- device scratch ----------------
__device__ __half g_Wc[(size_t)NL * 4 * HID * 2 * HID];  // [l][np][k] gate-interleaved, K-concat
__device__ __half g_thW[(size_t)2 * HID * HID];
__device__ float  g_biasc[NL * 4 * HID];
__device__ __half g_z16[(size_t)BAT * HID];
__device__ __half g_x0[(size_t)BAT * HID];
__device__ __half g_h[NL * 2][(size_t)BAT * HID];        // ping-pong per layer
__device__ float  g_c[NL][(size_t)BAT * HID];

// ---------------- helpers ----------------
__device__ __forceinline__ unsigned h2u(__half2 h) {
    return *(unsigned*)&h;
}
__device__ __forceinline__ uint32_t smem_u32(const void* p) {
    return (uint32_t)__cvta_generic_to_shared(p);
}
__device__ __forceinline__ void cp16(uint32_t s, const void* g) {
    asm volatile("cp.async.cg.shared.global [%0], [%1], 16;\n" :: "r"(s), "l"(g));
}
__device__ __forceinline__ void mma16816(float* d, const uint32_t* a, const uint32_t* b) {
    asm volatile(
        "mma.sync.aligned.m16n8k16.row.col.f32.f16.f16.f32 "
        "{%0,%1,%2,%3}, {%4,%5,%6,%7}, {%8,%9}, {%0,%1,%2,%3};\n"
        : "+f"(d[0]), "+f"(d[1]), "+f"(d[2]), "+f"(d[3])
        : "r"(a[0]), "r"(a[1]), "r"(a[2]), "r"(a[3]), "r"(b[0]), "r"(b[1]));
}
#define LDSM4(r, addr)                                                          \
    asm volatile("ldmatrix.sync.aligned.m8n8.x4.shared.b16 {%0,%1,%2,%3}, [%4];"\
        : "=r"((r)[0]), "=r"((r)[1]), "=r"((r)[2]), "=r"((r)[3]) : "r"(addr))

__device__ __forceinline__ int swz64(int r, int k) {
    return r * 64 + ((((k >> 3) ^ (r & 7)) << 3) | (k & 7));
}
__device__ __forceinline__ float sigf(float x) {
    return __fdividef(1.f, 1.f + __expf(-x));
}
__device__ __forceinline__ float tanhe(float x) {
    return __fdividef(2.f, 1.f + __expf(-2.f * x)) - 1.f;
}

// ---------------- GEMM body (R6/R13 exact, 32x32 warp tiles) ----------------
// CTA tile 128x128, 16 warps (4m x 4n), warp tile 32x32, 6-stage cp.async ring,
// one barrier per PAIR of 64-half k-tiles, register double-buffered fragments,
// XOR slice addressing.
template<int EPI>
__device__ __forceinline__ void gemm_dev(
    const __half* __restrict__ A0, const __half* __restrict__ A1,
    const __half* __restrict__ Bw, const float* __restrict__ bias,
    float* __restrict__ cptr, __half* __restrict__ hptr,
    float* __restrict__ yptr, const int KT, const int bm, const int bn,
    const uint32_t sb)
{
    const int tid = threadIdx.x, wid = tid >> 5, lane = tid & 31;
    const int g8 = lane >> 2, tig = lane & 3;
    const int wm = wid & 3, wn = wid >> 2;
    const int Kh = KT * 64;
    const int NP = KT >> 1;

    float acc[2][4][4];
    #pragma unroll
    for (int a = 0; a < 2; a++)
        #pragma unroll
        for (int b = 0; b < 4; b++)
            #pragma unroll
            for (int d = 0; d < 4; d++) acc[a][b][d] = 0.f;

    uint32_t aoff[2], boff[2];
    {
        int arow = lane & 15, ac = (lane >> 4) << 3;
        int brow = (lane & 7) + ((lane & 16) >> 1), bc = lane & 8;
        #pragma unroll
        for (int mt = 0; mt < 2; mt++)
            aoff[mt] = 2 * swz64(wm * 32 + mt * 16 + arow, ac);
        #pragma unroll
        for (int p = 0; p < 2; p++)
            boff[p] = A_BYTES + 2 * swz64(wn * 32 + p * 16 + brow, bc);
    }

    auto fill = [&](int kt) {
        int st = kt % NSTG;
        int k0 = kt << 6;
        const __half* Ap; int ks;
        if (k0 < HID) { Ap = A0; ks = k0; } else { Ap = A1; ks = k0 - HID; }
        uint32_t ab = sb + st * STG_BYTES, bb = ab + A_BYTES;
        #pragma unroll
        for (int i = 0; i < 2; i++) {
            int idx = tid + i * 512;
            int r = idx >> 3, cc = idx & 7;
            uint32_t off = 2 * swz64(r, cc << 3);
            cp16(ab + off, Ap + (size_t)(bm + r) * HID + ks + (cc << 3));
            cp16(bb + off, Bw + (size_t)(bn + r) * Kh + k0 + (cc << 3));
        }
    };

    fill(0); fill(1); asm volatile("cp.async.commit_group;\n");
    if (NP > 1) { fill(2); fill(3); asm volatile("cp.async.commit_group;\n"); }

    for (int i = 0; i < NP; i++) {
        if (i + 1 < NP) asm volatile("cp.async.wait_group 1;\n");
        else            asm volatile("cp.async.wait_group 0;\n");
        __syncthreads();
        if (i + 2 < NP) {
            fill(2 * i + 4); fill(2 * i + 5);
            asm volatile("cp.async.commit_group;\n");
        }

        const uint32_t base0 = sb + ((2 * i) % NSTG) * STG_BYTES;
        const uint32_t base1 = sb + ((2 * i + 1) % NSTG) * STG_BYTES;

        uint32_t af[2][2][4], bf[2][2][4];
        LDSM4(af[0][0], base0 + aoff[0]);
        LDSM4(af[0][1], base0 + aoff[1]);
        LDSM4(bf[0][0], base0 + boff[0]);
        LDSM4(bf[0][1], base0 + boff[1]);

        #pragma unroll
        for (int ss = 0; ss < 8; ss++) {
            const int cb = ss & 1, nb = cb ^ 1;
            if (ss < 7) {
                const int ns = ss + 1;
                const uint32_t nbase = (ns < 4) ? base0 : base1;
                const uint32_t x = (uint32_t)(ns & 3) << 5;
                LDSM4(af[nb][0], nbase + (aoff[0] ^ x));
                LDSM4(af[nb][1], nbase + (aoff[1] ^ x));
                LDSM4(bf[nb][0], nbase + (boff[0] ^ x));
                LDSM4(bf[nb][1], nbase + (boff[1] ^ x));
            }
            #pragma unroll
            for (int mt = 0; mt < 2; mt++) {
                #pragma unroll
                for (int p = 0; p < 2; p++) {
                    mma16816(acc[mt][2 * p],     af[cb][mt], &bf[cb][p][0]);
                    mma16816(acc[mt][2 * p + 1], af[cb][mt], &bf[cb][p][2]);
                }
            }
        }
    }

    if (EPI == 0) {
        #pragma unroll
        for (int p = 0; p < 2; p++) {
            int nb = bn + wn * 32 + p * 16 + 2 * tig;
            float bi = bias[nb], bff = bias[nb + 1], bg = bias[nb + 8], bo = bias[nb + 9];
            int u = (bn >> 2) + wn * 8 + p * 4 + tig;
            #pragma unroll
            for (int mt = 0; mt < 2; mt++) {
                #pragma unroll
                for (int hr = 0; hr < 2; hr++) {
                    int b = bm + wm * 32 + mt * 16 + g8 + hr * 8;
                    int d = hr * 2;
                    float ig = acc[mt][2 * p][d]         + bi;
                    float fg = acc[mt][2 * p][d + 1]     + bff;
                    float gg = acc[mt][2 * p + 1][d]     + bg;
                    float og = acc[mt][2 * p + 1][d + 1] + bo;
                    size_t ci = (size_t)b * HID + u;
                    float cn = sigf(fg) * cptr[ci] + sigf(ig) * tanhe(gg);
                    float hn = sigf(og) * tanhe(cn);
                    cptr[ci] = cn;
                    hptr[ci] = __float2half(hn);
                    if (yptr) yptr[ci] = hn;
                }
            }
        }
    } else {
        #pragma unroll
        for (int mt = 0; mt < 2; mt++) {
            int r0 = bm + wm * 32 + mt * 16 + g8;
            #pragma unroll
            for (int nt = 0; nt < 4; nt++) {
                int col = bn + wn * 32 + nt * 8 + 2 * tig;
                float b0 = bias[col], b1 = bias[col + 1];
                int l2 = col >> 10, j = col & (HID - 1);
                __half2 v0 = __floats2half2_rn(tanhe(acc[mt][nt][0] + b0),
                                               tanhe(acc[mt][nt][1] + b1));
                __half2 v1 = __floats2half2_rn(tanhe(acc[mt][nt][2] + b0),
                                               tanhe(acc[mt][nt][3] + b1));
                size_t lofs = (size_t)l2 * 2 * BAT * HID;   // ping buffer 0 of layer l2
                *(__half2*)(hptr + lofs + (size_t)r0 * HID + j)       = v0;
                *(__half2*)(hptr + lofs + (size_t)(r0 + 8) * HID + j) = v1;
            }
        }
    }
}

// ---------------- stage kernel (R6) ----------------
template<int EPI>
__global__ void __launch_bounds__(512)
lstm_gemm(const __half* __restrict__ A0, const __half* __restrict__ A1,
          const __half* __restrict__ Bw, const float* __restrict__ bias,
          float* __restrict__ cptr, __half* __restrict__ hptr,
          float* __restrict__ yptr, int KT)
{
    extern __shared__ __half sm[];
    gemm_dev<EPI>(A0, A1, Bw, bias, cptr, hptr, yptr, KT,
                  blockIdx.y * 128, blockIdx.x * 128, smem_u32(sm));
}

// ---------------- fused init GEMM + weight conversion ----------------
// CTAs 0..63: init projection h0 = tanh(z @ thW^T + thb) (16x4 tiles).
// CTAs 64..127: convert/interleave W to fp16 (vectorized, runs on other SMs).
__global__ void __launch_bounds__(512)
init_fused(const __half* __restrict__ z16v, const __half* __restrict__ thWc,
           const float* __restrict__ thb, __half* __restrict__ h,
           const float* __restrict__ Wih, const float* __restrict__ Whh)
{
    extern __shared__ __half sm[];
    const int cta = blockIdx.x;
    if (cta < 64) {
        gemm_dev<1>(z16v, z16v, thWc, thb, nullptr, h, nullptr, 16,
                    (cta >> 4) * 128, (cta & 15) * 128, smem_u32(sm));
    } else {
        // 4,194,304 float4-chunks over 64 CTAs x 512 threads
        const int NT = 64 * 512;
        int t0 = (cta - 64) * 512 + threadIdx.x;
        #pragma unroll 4
        for (int ch = t0; ch < NL * 4 * HID * (2 * HID) / 4; ch += NT) {
            int k4  = ch & 511;                      // 512 chunks per 2048-half row
            int row = ch >> 9;                       // l*4096 + np
            int np  = row & 4095, l = row >> 12;
            int within = np & 15, block = np >> 4;
            int gate = ((within & 8) ? 2 : 0) + (within & 1);
            int tg   = (within & 7) >> 1;
            int u = block * 4 + tg;
            size_t ln = ((size_t)l * 4 * HID + (size_t)gate * HID + u) * HID;
            const float4 v = (k4 < 256)
                ? *(const float4*)(Wih + ln + (k4 << 2))
                : *(const float4*)(Whh + ln + ((k4 - 256) << 2));
            uint2 o;
            o.x = h2u(__floats2half2_rn(v.x, v.y));
            o.y = h2u(__floats2half2_rn(v.z, v.w));
            *(uint2*)(g_Wc + ((size_t)ch << 2)) = o;
        }
    }
}

// ---------------- vectorized misc conversion ----------------
__global__ void convert_misc_v(const float* __restrict__ z, const float* __restrict__ thW,
                               const float* __restrict__ emb,
                               const float* __restrict__ bih, const float* __restrict__ bhh)
{
    const int stride = gridDim.x * blockDim.x;
    for (int ch = blockIdx.x * blockDim.x + threadIdx.x;
         ch < 2 * HID * HID / 4; ch += stride) {
        float4 v = *(const float4*)(thW + (ch << 2));
        uint2 o;
        o.x = h2u(__floats2half2_rn(v.x, v.y));
        o.y = h2u(__floats2half2_rn(v.z, v.w));
        *(uint2*)(g_thW + ((size_t)ch << 2)) = o;
        if (ch < BAT * HID / 4) {
            float4 zv = *(const float4*)(z + (ch << 2));
            uint2 zo;
            zo.x = h2u(__floats2half2_rn(zv.x, zv.y));
            zo.y = h2u(__floats2half2_rn(zv.z, zv.w));
            *(uint2*)(g_z16 + ((size_t)ch << 2)) = zo;
            float4 ev = *(const float4*)(emb + ((ch << 2) & (HID - 1)));
            uint2 eo;
            eo.x = h2u(__floats2half2_rn(ev.x, ev.y));
            eo.y = h2u(__floats2half2_rn(ev.z, ev.w));
            *(uint2*)(g_x0 + ((size_t)ch << 2)) = eo;
        }
        if (ch < NL * BAT * HID / 4)
            ((float4*)g_c)[ch] = make_float4(0.f, 0.f, 0.f, 0.f);
        if (ch < NL * 4 * HID / 4) {
            #pragma unroll
            for (int q = 0; q < 4; q++) {
                int idx = (ch << 2) + q;
                int l = idx >> 12, np = idx & 4095;
                int within = np & 15, block = np >> 4;
                int gate = ((within & 8) ? 2 : 0) + (within & 1);
                int tg   = (within & 7) >> 1;
                int u = block * 4 + tg;
                int src = l * 4 * HID + gate * HID + u;
                g_biasc[idx] = bih[src] + bhh[src];
            }
        }
    }
}

// ---------------- launch ----------------
extern "C" void kernel_launch(void* const* d_in, const int* in_sizes, int n_in,
                              void* d_out, int out_size)
{
    const float* z   = (const float*)d_in[0];
    const float* thW = (const float*)d_in[1];
    const float* thb = (const float*)d_in[2];
    const float* emb = (const float*)d_in[3];
    const float* Wih = (const float*)d_in[4];
    const float* Whh = (const float*)d_in[5];
    const float* bih = (const float*)d_in[6];
    const float* bhh = (const float*)d_in[7];
    float* out = (float*)d_out;

    __half *Wc, *thWc, *z16, *x0, *h;
    float *c, *biasc;
    cudaGetSymbolAddress((void**)&Wc,    g_Wc);
    cudaGetSymbolAddress((void**)&thWc,  g_thW);
    cudaGetSymbolAddress((void**)&z16,   g_z16);
    cudaGetSymbolAddress((void**)&x0,    g_x0);
    cudaGetSymbolAddress((void**)&h,     g_h);
    cudaGetSymbolAddress((void**)&c,     g_c);
    cudaGetSymbolAddress((void**)&biasc, g_biasc);

    cudaFuncSetAttribute(lstm_gemm<0>, cudaFuncAttributeMaxDynamicSharedMemorySize, SMEM_BYTES);
    cudaFuncSetAttribute(init_fused,   cudaFuncAttributeMaxDynamicSharedMemorySize, SMEM_BYTES);

    auto hb = [&](int l, int p) { return h + ((size_t)l * 2 + p) * BAT * HID; };

    convert_misc_v<<<512, 256>>>(z, thW, emb, bih, bhh);
    init_fused<<<128, 512, SMEM_BYTES>>>(z16, thWc, thb, h, Wih, Whh);

    for (int t = 0; t < TT; t++) {
        int p = t & 1;
        for (int l = 0; l < NL; l++) {
            const __half* Ain  = (l == 0) ? (t == 0 ? x0 : hb(1, p)) : hb(0, p ^ 1);
            const __half* Arec = hb(l, p);
            lstm_gemm<0><<<dim3(32, 4), 512, SMEM_BYTES>>>(
                Ain, Arec,
                Wc + (size_t)l * 4 * HID * 2 * HID,
                biasc + l * 4 * HID,
                c + (size_t)l * BAT * HID,
                hb(l, p ^ 1),
                (l == NL - 1) ? out + (size_t)t * BAT * HID : nullptr,
                32);
        }
    }
}

// round 17
// speedup vs baseline: 1.1220x; 1.0016x over previous
#include <cuda_runtime.h>
#include <cuda_fp16.h>
#include <cstdint>
#include <cstddef>

#define HID 1024
#define BAT 512
#define NL  2
#define TT  32

#define A_BYTES   16384          // 128 rows x 64 halves
#define STG_BYTES 32768          // A + B
#define NSTG 6
#define SMEM_BYTES (NSTG * STG_BYTES)   // 196608, 1 CTA/SM

// ---------------- device scratch ----------------
__device__ __half g_Wc[(size_t)NL * 4 * HID * 2 * HID];  // [l][np][k] gate-interleaved, K-concat
__device__ __half g_thW[(size_t)2 * HID * HID];
__device__ float  g_biasc[NL * 4 * HID];
__device__ __half g_z16[(size_t)BAT * HID];
__device__ __half g_x0[(size_t)BAT * HID];
__device__ __half g_h[NL * 2][(size_t)BAT * HID];        // ping-pong per layer
__device__ float  g_c[NL][(size_t)BAT * HID];

// ---------------- helpers ----------------
__device__ __forceinline__ unsigned h2u(__half2 h) {
    return *(unsigned*)&h;
}
__device__ __forceinline__ uint32_t smem_u32(const void* p) {
    return (uint32_t)__cvta_generic_to_shared(p);
}
__device__ __forceinline__ void cp16(uint32_t s, const void* g) {
    asm volatile("cp.async.cg.shared.global [%0], [%1], 16;\n" :: "r"(s), "l"(g));
}
__device__ __forceinline__ void mma16816(float* d, const uint32_t* a, const uint32_t* b) {
    asm volatile(
        "mma.sync.aligned.m16n8k16.row.col.f32.f16.f16.f32 "
        "{%0,%1,%2,%3}, {%4,%5,%6,%7}, {%8,%9}, {%0,%1,%2,%3};\n"
        : "+f"(d[0]), "+f"(d[1]), "+f"(d[2]), "+f"(d[3])
        : "r"(a[0]), "r"(a[1]), "r"(a[2]), "r"(a[3]), "r"(b[0]), "r"(b[1]));
}
#define LDSM4(r, addr)                                                          \
    asm volatile("ldmatrix.sync.aligned.m8n8.x4.shared.b16 {%0,%1,%2,%3}, [%4];"\
        : "=r"((r)[0]), "=r"((r)[1]), "=r"((r)[2]), "=r"((r)[3]) : "r"(addr))

__device__ __forceinline__ int swz64(int r, int k) {
    return r * 64 + ((((k >> 3) ^ (r & 7)) << 3) | (k & 7));
}
__device__ __forceinline__ float sigf(float x) {
    return __fdividef(1.f, 1.f + __expf(-x));
}
__device__ __forceinline__ float tanhe(float x) {
    return __fdividef(2.f, 1.f + __expf(-2.f * x)) - 1.f;
}

// ---------------- GEMM body (R6 exact, 32x32 warp tiles) ----------------
// CTA tile 128x128, 16 warps (4m x 4n), warp tile 32x32, 6-stage cp.async ring,
// one barrier per PAIR of 64-half k-tiles, register double-buffered fragments,
// XOR slice addressing.
template<int EPI>
__device__ __forceinline__ void gemm_dev(
    const __half* __restrict__ A0, const __half* __restrict__ A1,
    const __half* __restrict__ Bw, const float* __restrict__ bias,
    float* __restrict__ cptr, __half* __restrict__ hptr,
    float* __restrict__ yptr, const int KT, const int bm, const int bn,
    const uint32_t sb)
{
    const int tid = threadIdx.x, wid = tid >> 5, lane = tid & 31;
    const int g8 = lane >> 2, tig = lane & 3;
    const int wm = wid & 3, wn = wid >> 2;
    const int Kh = KT * 64;
    const int NP = KT >> 1;

    float acc[2][4][4];
    #pragma unroll
    for (int a = 0; a < 2; a++)
        #pragma unroll
        for (int b = 0; b < 4; b++)
            #pragma unroll
            for (int d = 0; d < 4; d++) acc[a][b][d] = 0.f;

    uint32_t aoff[2], boff[2];
    {
        int arow = lane & 15, ac = (lane >> 4) << 3;
        int brow = (lane & 7) + ((lane & 16) >> 1), bc = lane & 8;
        #pragma unroll
        for (int mt = 0; mt < 2; mt++)
            aoff[mt] = 2 * swz64(wm * 32 + mt * 16 + arow, ac);
        #pragma unroll
        for (int p = 0; p < 2; p++)
            boff[p] = A_BYTES + 2 * swz64(wn * 32 + p * 16 + brow, bc);
    }

    auto fill = [&](int kt) {
        int st = kt % NSTG;
        int k0 = kt << 6;
        const __half* Ap; int ks;
        if (k0 < HID) { Ap = A0; ks = k0; } else { Ap = A1; ks = k0 - HID; }
        uint32_t ab = sb + st * STG_BYTES, bb = ab + A_BYTES;
        #pragma unroll
        for (int i = 0; i < 2; i++) {
            int idx = tid + i * 512;
            int r = idx >> 3, cc = idx & 7;
            uint32_t off = 2 * swz64(r, cc << 3);
            cp16(ab + off, Ap + (size_t)(bm + r) * HID + ks + (cc << 3));
            cp16(bb + off, Bw + (size_t)(bn + r) * Kh + k0 + (cc << 3));
        }
    };

    fill(0); fill(1); asm volatile("cp.async.commit_group;\n");
    if (NP > 1) { fill(2); fill(3); asm volatile("cp.async.commit_group;\n"); }

    for (int i = 0; i < NP; i++) {
        if (i + 1 < NP) asm volatile("cp.async.wait_group 1;\n");
        else            asm volatile("cp.async.wait_group 0;\n");
        __syncthreads();
        if (i + 2 < NP) {
            fill(2 * i + 4); fill(2 * i + 5);
            asm volatile("cp.async.commit_group;\n");
        }

        const uint32_t base0 = sb + ((2 * i) % NSTG) * STG_BYTES;
        const uint32_t base1 = sb + ((2 * i + 1) % NSTG) * STG_BYTES;

        uint32_t af[2][2][4], bf[2][2][4];
        LDSM4(af[0][0], base0 + aoff[0]);
        LDSM4(af[0][1], base0 + aoff[1]);
        LDSM4(bf[0][0], base0 + boff[0]);
        LDSM4(bf[0][1], base0 + boff[1]);

        #pragma unroll
        for (int ss = 0; ss < 8; ss++) {
            const int cb = ss & 1, nb = cb ^ 1;
            if (ss < 7) {
                const int ns = ss + 1;
                const uint32_t nbase = (ns < 4) ? base0 : base1;
                const uint32_t x = (uint32_t)(ns & 3) << 5;
                LDSM4(af[nb][0], nbase + (aoff[0] ^ x));
                LDSM4(af[nb][1], nbase + (aoff[1] ^ x));
                LDSM4(bf[nb][0], nbase + (boff[0] ^ x));
                LDSM4(bf[nb][1], nbase + (boff[1] ^ x));
            }
            #pragma unroll
            for (int mt = 0; mt < 2; mt++) {
                #pragma unroll
                for (int p = 0; p < 2; p++) {
                    mma16816(acc[mt][2 * p],     af[cb][mt], &bf[cb][p][0]);
                    mma16816(acc[mt][2 * p + 1], af[cb][mt], &bf[cb][p][2]);
                }
            }
        }
    }

    if (EPI == 0) {
        #pragma unroll
        for (int p = 0; p < 2; p++) {
            int nb = bn + wn * 32 + p * 16 + 2 * tig;
            float bi = bias[nb], bff = bias[nb + 1], bg = bias[nb + 8], bo = bias[nb + 9];
            int u = (bn >> 2) + wn * 8 + p * 4 + tig;
            #pragma unroll
            for (int mt = 0; mt < 2; mt++) {
                #pragma unroll
                for (int hr = 0; hr < 2; hr++) {
                    int b = bm + wm * 32 + mt * 16 + g8 + hr * 8;
                    int d = hr * 2;
                    float ig = acc[mt][2 * p][d]         + bi;
                    float fg = acc[mt][2 * p][d + 1]     + bff;
                    float gg = acc[mt][2 * p + 1][d]     + bg;
                    float og = acc[mt][2 * p + 1][d + 1] + bo;
                    size_t ci = (size_t)b * HID + u;
                    float cn = sigf(fg) * cptr[ci] + sigf(ig) * tanhe(gg);
                    float hn = sigf(og) * tanhe(cn);
                    cptr[ci] = cn;
                    hptr[ci] = __float2half(hn);
                    if (yptr) yptr[ci] = hn;
                }
            }
        }
    } else {
        #pragma unroll
        for (int mt = 0; mt < 2; mt++) {
            int r0 = bm + wm * 32 + mt * 16 + g8;
            #pragma unroll
            for (int nt = 0; nt < 4; nt++) {
                int col = bn + wn * 32 + nt * 8 + 2 * tig;
                float b0 = bias[col], b1 = bias[col + 1];
                int l2 = col >> 10, j = col & (HID - 1);
                __half2 v0 = __floats2half2_rn(tanhe(acc[mt][nt][0] + b0),
                                               tanhe(acc[mt][nt][1] + b1));
                __half2 v1 = __floats2half2_rn(tanhe(acc[mt][nt][2] + b0),
                                               tanhe(acc[mt][nt][3] + b1));
                size_t lofs = (size_t)l2 * 2 * BAT * HID;   // ping buffer 0 of layer l2
                *(__half2*)(hptr + lofs + (size_t)r0 * HID + j)       = v0;
                *(__half2*)(hptr + lofs + (size_t)(r0 + 8) * HID + j) = v1;
            }
        }
    }
}

// ---------------- stage kernel (R6) ----------------
template<int EPI>
__global__ void __launch_bounds__(512)
lstm_gemm(const __half* __restrict__ A0, const __half* __restrict__ A1,
          const __half* __restrict__ Bw, const float* __restrict__ bias,
          float* __restrict__ cptr, __half* __restrict__ hptr,
          float* __restrict__ yptr, int KT)
{
    extern __shared__ __half sm[];
    gemm_dev<EPI>(A0, A1, Bw, bias, cptr, hptr, yptr, KT,
                  blockIdx.y * 128, blockIdx.x * 128, smem_u32(sm));
}

// ---------------- fused init GEMM + weight conversion (148 CTAs) ------------
// CTAs 0..63: init projection h0 = tanh(z @ thW^T + thb) (16x4 tiles).
// CTAs 64..147: convert/interleave W to fp16 (vectorized) + zero g_c.
__global__ void __launch_bounds__(512)
init_fused(const __half* __restrict__ z16v, const __half* __restrict__ thWc,
           const float* __restrict__ thb, __half* __restrict__ h,
           const float* __restrict__ Wih, const float* __restrict__ Whh)
{
    extern __shared__ __half sm[];
    const int cta = blockIdx.x;
    if (cta < 64) {
        gemm_dev<1>(z16v, z16v, thWc, thb, nullptr, h, nullptr, 16,
                    (cta >> 4) * 128, (cta & 15) * 128, smem_u32(sm));
    } else {
        const int NCV = 84;                          // convert CTAs
        const int NT = NCV * 512;
        int t0 = (cta - 64) * 512 + threadIdx.x;
        // zero c: 1M floats = 256K float4
        for (int ch = t0; ch < NL * BAT * HID / 4; ch += NT)
            ((float4*)g_c)[ch] = make_float4(0.f, 0.f, 0.f, 0.f);
        // 4,194,304 float4-chunks of W
        #pragma unroll 4
        for (int ch = t0; ch < NL * 4 * HID * (2 * HID) / 4; ch += NT) {
            int k4  = ch & 511;                      // 512 chunks per 2048-half row
            int row = ch >> 9;                       // l*4096 + np
            int np  = row & 4095, l = row >> 12;
            int within = np & 15, block = np >> 4;
            int gate = ((within & 8) ? 2 : 0) + (within & 1);
            int tg   = (within & 7) >> 1;
            int u = block * 4 + tg;
            size_t ln = ((size_t)l * 4 * HID + (size_t)gate * HID + u) * HID;
            const float4 v = (k4 < 256)
                ? *(const float4*)(Wih + ln + (k4 << 2))
                : *(const float4*)(Whh + ln + ((k4 - 256) << 2));
            uint2 o;
            o.x = h2u(__floats2half2_rn(v.x, v.y));
            o.y = h2u(__floats2half2_rn(v.z, v.w));
            *(uint2*)(g_Wc + ((size_t)ch << 2)) = o;
        }
    }
}

// ---------------- vectorized misc conversion (thW, z, x0, biases) -----------
__global__ void convert_misc_v(const float* __restrict__ z, const float* __restrict__ thW,
                               const float* __restrict__ emb,
                               const float* __restrict__ bih, const float* __restrict__ bhh)
{
    const int stride = gridDim.x * blockDim.x;
    for (int ch = blockIdx.x * blockDim.x + threadIdx.x;
         ch < 2 * HID * HID / 4; ch += stride) {
        float4 v = *(const float4*)(thW + (ch << 2));
        uint2 o;
        o.x = h2u(__floats2half2_rn(v.x, v.y));
        o.y = h2u(__floats2half2_rn(v.z, v.w));
        *(uint2*)(g_thW + ((size_t)ch << 2)) = o;
        if (ch < BAT * HID / 4) {
            float4 zv = *(const float4*)(z + (ch << 2));
            uint2 zo;
            zo.x = h2u(__floats2half2_rn(zv.x, zv.y));
            zo.y = h2u(__floats2half2_rn(zv.z, zv.w));
            *(uint2*)(g_z16 + ((size_t)ch << 2)) = zo;
            float4 ev = *(const float4*)(emb + ((ch << 2) & (HID - 1)));
            uint2 eo;
            eo.x = h2u(__floats2half2_rn(ev.x, ev.y));
            eo.y = h2u(__floats2half2_rn(ev.z, ev.w));
            *(uint2*)(g_x0 + ((size_t)ch << 2)) = eo;
        }
        if (ch < NL * 4 * HID / 4) {
            #pragma unroll
            for (int q = 0; q < 4; q++) {
                int idx = (ch << 2) + q;
                int l = idx >> 12, np = idx & 4095;
                int within = np & 15, block = np >> 4;
                int gate = ((within & 8) ? 2 : 0) + (within & 1);
                int tg   = (within & 7) >> 1;
                int u = block * 4 + tg;
                int src = l * 4 * HID + gate * HID + u;
                g_biasc[idx] = bih[src] + bhh[src];
            }
        }
    }
}

// ---------------- launch ----------------
extern "C" void kernel_launch(void* const* d_in, const int* in_sizes, int n_in,
                              void* d_out, int out_size)
{
    const float* z   = (const float*)d_in[0];
    const float* thW = (const float*)d_in[1];
    const float* thb = (const float*)d_in[2];
    const float* emb = (const float*)d_in[3];
    const float* Wih = (const float*)d_in[4];
    const float* Whh = (const float*)d_in[5];
    const float* bih = (const float*)d_in[6];
    const float* bhh = (const float*)d_in[7];
    float* out = (float*)d_out;

    __half *Wc, *thWc, *z16, *x0, *h;
    float *c, *biasc;
    cudaGetSymbolAddress((void**)&Wc,    g_Wc);
    cudaGetSymbolAddress((void**)&thWc,  g_thW);
    cudaGetSymbolAddress((void**)&z16,   g_z16);
    cudaGetSymbolAddress((void**)&x0,    g_x0);
    cudaGetSymbolAddress((void**)&h,     g_h);
    cudaGetSymbolAddress((void**)&c,     g_c);
    cudaGetSymbolAddress((void**)&biasc, g_biasc);

    cudaFuncSetAttribute(lstm_gemm<0>, cudaFuncAttributeMaxDynamicSharedMemorySize, SMEM_BYTES);
    cudaFuncSetAttribute(init_fused,   cudaFuncAttributeMaxDynamicSharedMemorySize, SMEM_BYTES);

    auto hb = [&](int l, int p) { return h + ((size_t)l * 2 + p) * BAT * HID; };

    convert_misc_v<<<512, 256>>>(z, thW, emb, bih, bhh);
    init_fused<<<148, 512, SMEM_BYTES>>>(z16, thWc, thb, h, Wih, Whh);

    for (int t = 0; t < TT; t++) {
        int p = t & 1;
        for (int l = 0; l < NL; l++) {
            const __half* Ain  = (l == 0) ? (t == 0 ? x0 : hb(1, p)) : hb(0, p ^ 1);
            const __half* Arec = hb(l, p);
            lstm_gemm<0><<<dim3(32, 4), 512, SMEM_BYTES>>>(
                Ain, Arec,
                Wc + (size_t)l * 4 * HID * 2 * HID,
                biasc + l * 4 * HID,
                c + (size_t)l * BAT * HID,
                hb(l, p ^ 1),
                (l == NL - 1) ? out + (size_t)t * BAT * HID : nullptr,
                32);
        }
    }
}